// round 16
// baseline (speedup 1.0000x reference)
#include <cuda_runtime.h>
#include <cstdint>

// ============================================================================
// out[8192,4096] = sign(x[8192,4096]) @ sign(w[4096,4096])
// Binary GEMM, exact:  dot = 4096 - 2*popc(xbits ^ wbits).
//
// R15: PIPE-BALANCED counting. Profile-derived model (3 rounds consistent):
//   POPC = quarter-rate (rt8) on its own unit; XOR/LOP3 = rt2 alu; IMAD = fma.
//   - pure naive  (R13/14): popc-bound  -> 870us GEMM
//   - pure CSA    (R12)   : alu-bound   -> 924us GEMM
//   Mix 22 CSA-groups + 10 naive-groups per K: alu 520 cyc == popc 496 cyc.
// ============================================================================

static constexpr int MDIM = 8192;
static constexpr int NDIM = 4096;
static constexpr int KDIM = 4096;
static constexpr int KW   = KDIM / 32;   // 128 words per row

static constexpr int MT = MDIM / 64;     // 128
static constexpr int NT = NDIM / 64;     // 64

// Packed bit scratch, word-major per tile:
__device__ __align__(16) uint32_t g_xbits[(size_t)MT * KW * 64];   // 4 MB
__device__ __align__(16) uint32_t g_wbits[(size_t)NT * KW * 64];   // 2 MB

// ---------------------------------------------------------------------------
__device__ __forceinline__ uint32_t smem_u32(const void* p) {
    uint32_t a;
    asm("{ .reg .u64 t; cvta.to.shared.u64 t, %1; cvt.u32.u64 %0, t; }" : "=r"(a) : "l"(p));
    return a;
}
__device__ __forceinline__ void cpasync16(uint32_t s, const void* g) {
    asm volatile("cp.async.cg.shared.global [%0], [%1], 16;" :: "r"(s), "l"(g));
}
#define CP_COMMIT() asm volatile("cp.async.commit_group;" ::: "memory")
#define CP_WAITN(n) asm volatile("cp.async.wait_group %0;" :: "n"(n) : "memory")

// ---------------------------------------------------------------------------
// Fused prepass (unchanged).
// ---------------------------------------------------------------------------
__global__ void __launch_bounds__(256) k_pack(const float* __restrict__ x,
                                             const float* __restrict__ w) {
    if (blockIdx.x < 1024) {
        int m    = blockIdx.x * 8 + (threadIdx.x >> 5);
        int lane = threadIdx.x & 31;
        const float* row = x + (size_t)m * KDIM;
        uint32_t mt = (uint32_t)m >> 6, ml = (uint32_t)m & 63u;
        uint32_t* dst = g_xbits + (size_t)mt * (KW * 64) + ml;
        #pragma unroll 4
        for (int wi = 0; wi < KW; wi++) {
            float v = row[wi * 32 + lane];
            uint32_t bits = __ballot_sync(0xffffffffu, v < 0.0f);
            if (lane == 0) dst[(size_t)wi * 64] = bits;
        }
    } else {
        uint32_t q  = (blockIdx.x - 1024u) * 256u + threadIdx.x;
        uint32_t nl = q & 63u;
        uint32_t W  = (q >> 6) & 127u;
        uint32_t nt = q >> 13;
        uint32_t n  = nt * 64u + nl;
        uint32_t kb = W * 32u;
        uint32_t bits = 0;
        #pragma unroll
        for (int j = 0; j < 32; j++) {
            float v = w[(size_t)(kb + j) * NDIM + n];
            bits |= (v < 0.0f ? 1u : 0u) << j;
        }
        g_wbits[q] = bits;
    }
}

// ---------------------------------------------------------------------------
// Binary GEMM: 64x64 tile, 256 threads, 16 outputs/thread (4m x 4n).
// Whole K in smem; per half (64 words): 5 super-groups of (CSA,CSA,naive)
// + 1 CSA group = 11 CSA + 5 naive -> per K: 22 CSA / 10 naive.
// ---------------------------------------------------------------------------
__global__ void __launch_bounds__(256, 2) k_bgemm(float* __restrict__ out) {
    extern __shared__ uint32_t sm[];                 // [A: 128*64 | B: 128*64]
    uint32_t* smA = sm;
    uint32_t* smB = sm + KW * 64;
    const uint32_t sbA = smem_u32(smA);
    const uint32_t sbB = smem_u32(smB);

    const int tid  = threadIdx.x;
    const int warp = tid >> 5;
    const int lane = tid & 31;
    const int mrow = (warp >> 2) * 32 + ((lane >> 2) * 4);
    const int ncol = (warp & 3) * 16 + ((lane & 3) * 4);

    const uint32_t bid = blockIdx.x;
    const uint32_t ntb = bid & 63u;
    const uint32_t mtb = bid >> 6;

    // Opaque constants so accumulates stay on the FMA pipe (IMAD).
    const uint32_t one  = (bid >> 28) + 1u;
    const uint32_t four = (bid >> 28) + 4u;

    const char* aG = (const char*)(g_xbits + (size_t)mtb * (KW * 64));
    const char* bG = (const char*)(g_wbits + (size_t)ntb * (KW * 64));

    #pragma unroll
    for (int h = 0; h < 2; h++) {
        #pragma unroll
        for (int i = 0; i < 4; i++) {
            int c = tid + i * 256;
            cpasync16(sbA + (uint32_t)(h * 16384 + c * 16), aG + (size_t)h * 16384 + (size_t)c * 16);
            cpasync16(sbB + (uint32_t)(h * 16384 + c * 16), bG + (size_t)h * 16384 + (size_t)c * 16);
        }
        CP_COMMIT();
    }

    uint32_t ones[16], twos[16], acc[16];
    #pragma unroll
    for (int o = 0; o < 16; o++) { ones[o] = 0; twos[o] = 0; acc[o] = 0; }

    // --- group processors (4 words each) ---
    auto load4 = [&](int gw, uint32_t av[4][4], uint32_t bv[4][4]) {
        #pragma unroll
        for (int w4 = 0; w4 < 4; w4++) {
            uint4 A = *reinterpret_cast<const uint4*>(smA + (gw + w4) * 64 + mrow);
            uint4 B = *reinterpret_cast<const uint4*>(smB + (gw + w4) * 64 + ncol);
            av[0][w4] = A.x; av[1][w4] = A.y; av[2][w4] = A.z; av[3][w4] = A.w;
            bv[0][w4] = B.x; bv[1][w4] = B.y; bv[2][w4] = B.z; bv[3][w4] = B.w;
        }
    };

    auto csa4 = [&](int gw) {
        uint32_t av[4][4], bv[4][4];
        load4(gw, av, bv);
        #pragma unroll
        for (int mf = 0; mf < 4; mf++) {
            #pragma unroll
            for (int nf = 0; nf < 4; nf++) {
                const int o = mf * 4 + nf;
                uint32_t x0 = av[mf][0] ^ bv[nf][0];
                uint32_t x1 = av[mf][1] ^ bv[nf][1];
                uint32_t x2 = av[mf][2] ^ bv[nf][2];
                uint32_t x3 = av[mf][3] ^ bv[nf][3];
                uint32_t t0 = (ones[o] & x0) | (ones[o] & x1) | (x0 & x1);
                ones[o] = ones[o] ^ x0 ^ x1;
                uint32_t t1 = (ones[o] & x2) | (ones[o] & x3) | (x2 & x3);
                ones[o] = ones[o] ^ x2 ^ x3;
                uint32_t f = (twos[o] & t0) | (twos[o] & t1) | (t0 & t1);
                twos[o] = twos[o] ^ t0 ^ t1;
                uint32_t pc = (uint32_t)__popc(f);
                asm("mad.lo.u32 %0, %1, %2, %0;" : "+r"(acc[o]) : "r"(pc), "r"(four));
            }
        }
    };

    auto naive4 = [&](int gw) {
        uint32_t av[4][4], bv[4][4];
        load4(gw, av, bv);
        #pragma unroll
        for (int mf = 0; mf < 4; mf++) {
            #pragma unroll
            for (int nf = 0; nf < 4; nf++) {
                const int o = mf * 4 + nf;
                #pragma unroll
                for (int w4 = 0; w4 < 4; w4++) {
                    uint32_t pc = (uint32_t)__popc(av[mf][w4] ^ bv[nf][w4]);
                    asm("mad.lo.u32 %0, %1, %2, %0;" : "+r"(acc[o]) : "r"(pc), "r"(one));
                }
            }
        }
    };

    CP_WAITN(1);
    __syncthreads();

    #pragma unroll 2
    for (int half = 0; half < 2; half++) {
        if (half == 1) { CP_WAITN(0); __syncthreads(); }
        const int base = half * 64;
        // 5 super-groups of 12 words: CSA, CSA, naive
        for (int sg = 0; sg < 5; sg++) {
            const int gw = base + sg * 12;
            csa4(gw);
            csa4(gw + 4);
            naive4(gw + 8);
        }
        // remainder 4 words: CSA
        csa4(base + 60);
    }

    // Epilogue: D = acc (naive + 4*fours) + 2*popc(twos) + popc(ones).
    const uint32_t m0 = mtb * 64u + (uint32_t)mrow;
    const uint32_t n0 = ntb * 64u + (uint32_t)ncol;
    #pragma unroll
    for (int mf = 0; mf < 4; mf++) {
        const int o = mf * 4;
        int D0 = (int)acc[o+0] + (__popc(twos[o+0]) << 1) + __popc(ones[o+0]);
        int D1 = (int)acc[o+1] + (__popc(twos[o+1]) << 1) + __popc(ones[o+1]);
        int D2 = (int)acc[o+2] + (__popc(twos[o+2]) << 1) + __popc(ones[o+2]);
        int D3 = (int)acc[o+3] + (__popc(twos[o+3]) << 1) + __popc(ones[o+3]);
        *reinterpret_cast<float4*>(out + (size_t)(m0 + (uint32_t)mf) * NDIM + n0) =
            make_float4((float)(KDIM - 2 * D0), (float)(KDIM - 2 * D1),
                        (float)(KDIM - 2 * D2), (float)(KDIM - 2 * D3));
    }
}

// ---------------------------------------------------------------------------
// Launch
// ---------------------------------------------------------------------------
extern "C" void kernel_launch(void* const* d_in, const int* in_sizes, int n_in,
                              void* d_out, int out_size) {
    const float* x = (const float*)d_in[0];   // [8192, 4096]
    const float* w = (const float*)d_in[1];   // [4096, 4096] (k-major)
    float* out = (float*)d_out;               // [8192, 4096]
    (void)in_sizes; (void)n_in; (void)out_size;

    static constexpr int SMEM = 2 * KW * 64 * 4;   // 65536 B
    cudaFuncSetAttribute(k_bgemm, cudaFuncAttributeMaxDynamicSharedMemorySize, SMEM);

    k_pack<<<3072, 256>>>(x, w);                   // fused x+w pack
    k_bgemm<<<MT * NT, 256, SMEM>>>(out);          // 8192 blocks
}

// round 17
// speedup vs baseline: 1.6717x; 1.6717x over previous
#include <cuda_runtime.h>
#include <cstdint>

// ============================================================================
// out[8192,4096] = sign(x[8192,4096]) @ sign(w[4096,4096])
// Binary GEMM, exact:  dot = 4096 - 2*popc(xbits ^ wbits).
//
// R16: pipe-balanced CSA/naive mix, FLAT codegen (R15's lambda/loop version
// regressed from codegen, not model). Rates (3-round-consistent model):
//   XOR/LOP3 rt2 (alu) | POPC rt8 (own hidden pipe) | IMAD (fma pipe).
// Per half: 16 groups of 4 words; grp%3==2 -> naive (4 XOR + 4 POPC),
// else CSA (10 alu + 1 POPC).  Per K: alu 8320 cyc ~ popc 7936 cyc.
// ============================================================================

static constexpr int MDIM = 8192;
static constexpr int NDIM = 4096;
static constexpr int KDIM = 4096;
static constexpr int KW   = KDIM / 32;   // 128 words per row

static constexpr int MT = MDIM / 64;     // 128
static constexpr int NT = NDIM / 64;     // 64

__device__ __align__(16) uint32_t g_xbits[(size_t)MT * KW * 64];   // 4 MB
__device__ __align__(16) uint32_t g_wbits[(size_t)NT * KW * 64];   // 2 MB

// ---------------------------------------------------------------------------
__device__ __forceinline__ uint32_t smem_u32(const void* p) {
    uint32_t a;
    asm("{ .reg .u64 t; cvta.to.shared.u64 t, %1; cvt.u32.u64 %0, t; }" : "=r"(a) : "l"(p));
    return a;
}
__device__ __forceinline__ void cpasync16(uint32_t s, const void* g) {
    asm volatile("cp.async.cg.shared.global [%0], [%1], 16;" :: "r"(s), "l"(g));
}
#define CP_COMMIT() asm volatile("cp.async.commit_group;" ::: "memory")
#define CP_WAITN(n) asm volatile("cp.async.wait_group %0;" :: "n"(n) : "memory")

// ---------------------------------------------------------------------------
// Fused prepass (unchanged, proven).
// ---------------------------------------------------------------------------
__global__ void __launch_bounds__(256) k_pack(const float* __restrict__ x,
                                             const float* __restrict__ w) {
    if (blockIdx.x < 1024) {
        int m    = blockIdx.x * 8 + (threadIdx.x >> 5);
        int lane = threadIdx.x & 31;
        const float* row = x + (size_t)m * KDIM;
        uint32_t mt = (uint32_t)m >> 6, ml = (uint32_t)m & 63u;
        uint32_t* dst = g_xbits + (size_t)mt * (KW * 64) + ml;
        #pragma unroll 4
        for (int wi = 0; wi < KW; wi++) {
            float v = row[wi * 32 + lane];
            uint32_t bits = __ballot_sync(0xffffffffu, v < 0.0f);
            if (lane == 0) dst[(size_t)wi * 64] = bits;
        }
    } else {
        uint32_t q  = (blockIdx.x - 1024u) * 256u + threadIdx.x;
        uint32_t nl = q & 63u;
        uint32_t W  = (q >> 6) & 127u;
        uint32_t nt = q >> 13;
        uint32_t n  = nt * 64u + nl;
        uint32_t kb = W * 32u;
        uint32_t bits = 0;
        #pragma unroll
        for (int j = 0; j < 32; j++) {
            float v = w[(size_t)(kb + j) * NDIM + n];
            bits |= (v < 0.0f ? 1u : 0u) << j;
        }
        g_wbits[q] = bits;
    }
}

// ---------------------------------------------------------------------------
// Binary GEMM: 64x64 tile, 256 threads, 16 outputs/thread (4m x 4n).
// Whole K resident in smem; flat fully-unrolled mixed counting loop.
// ---------------------------------------------------------------------------
__global__ void __launch_bounds__(256, 2) k_bgemm(float* __restrict__ out) {
    extern __shared__ uint32_t sm[];                 // [A: 128*64 | B: 128*64]
    uint32_t* smA = sm;
    uint32_t* smB = sm + KW * 64;
    const uint32_t sbA = smem_u32(smA);
    const uint32_t sbB = smem_u32(smB);

    const int tid  = threadIdx.x;
    const int warp = tid >> 5;
    const int lane = tid & 31;
    const int mrow = (warp >> 2) * 32 + ((lane >> 2) * 4);
    const int ncol = (warp & 3) * 16 + ((lane & 3) * 4);

    const uint32_t bid = blockIdx.x;
    const uint32_t ntb = bid & 63u;
    const uint32_t mtb = bid >> 6;

    // Opaque constants keep accumulates on the FMA pipe (IMAD).
    const uint32_t one  = (bid >> 28) + 1u;
    const uint32_t four = (bid >> 28) + 4u;

    const char* aG = (const char*)(g_xbits + (size_t)mtb * (KW * 64));
    const char* bG = (const char*)(g_wbits + (size_t)ntb * (KW * 64));

    #pragma unroll
    for (int h = 0; h < 2; h++) {
        #pragma unroll
        for (int i = 0; i < 4; i++) {
            int c = tid + i * 256;
            cpasync16(sbA + (uint32_t)(h * 16384 + c * 16), aG + (size_t)h * 16384 + (size_t)c * 16);
            cpasync16(sbB + (uint32_t)(h * 16384 + c * 16), bG + (size_t)h * 16384 + (size_t)c * 16);
        }
        CP_COMMIT();
    }

    uint32_t ones[16], twos[16], acc[16];
    #pragma unroll
    for (int o = 0; o < 16; o++) { ones[o] = 0; twos[o] = 0; acc[o] = 0; }

    CP_WAITN(1);
    __syncthreads();

    #pragma unroll 2
    for (int half = 0; half < 2; half++) {
        if (half == 1) { CP_WAITN(0); __syncthreads(); }

        #pragma unroll
        for (int grp = 0; grp < 16; grp++) {         // FULL unroll: grp static
            const int gw = half * 64 + grp * 4;
            uint32_t av[4][4], bv[4][4];
            #pragma unroll
            for (int w4 = 0; w4 < 4; w4++) {
                uint4 A = *reinterpret_cast<const uint4*>(smA + (gw + w4) * 64 + mrow);
                uint4 B = *reinterpret_cast<const uint4*>(smB + (gw + w4) * 64 + ncol);
                av[0][w4] = A.x; av[1][w4] = A.y; av[2][w4] = A.z; av[3][w4] = A.w;
                bv[0][w4] = B.x; bv[1][w4] = B.y; bv[2][w4] = B.z; bv[3][w4] = B.w;
            }

            if (grp % 3 == 2) {
                // NAIVE group: 4 XOR (alu) + 4 POPC (popc pipe) + 4 IMAD (fma).
                #pragma unroll
                for (int mf = 0; mf < 4; mf++) {
                    #pragma unroll
                    for (int nf = 0; nf < 4; nf++) {
                        const int o = mf * 4 + nf;
                        #pragma unroll
                        for (int w4 = 0; w4 < 4; w4++) {
                            uint32_t pc = (uint32_t)__popc(av[mf][w4] ^ bv[nf][w4]);
                            asm("mad.lo.u32 %0, %1, %2, %0;" : "+r"(acc[o]) : "r"(pc), "r"(one));
                        }
                    }
                }
            } else {
                // CSA group: 4 XOR + 6 LOP3 (alu) + 1 POPC + 1 IMAD (weight 4).
                #pragma unroll
                for (int mf = 0; mf < 4; mf++) {
                    #pragma unroll
                    for (int nf = 0; nf < 4; nf++) {
                        const int o = mf * 4 + nf;
                        uint32_t x0 = av[mf][0] ^ bv[nf][0];
                        uint32_t x1 = av[mf][1] ^ bv[nf][1];
                        uint32_t x2 = av[mf][2] ^ bv[nf][2];
                        uint32_t x3 = av[mf][3] ^ bv[nf][3];
                        uint32_t t0 = (ones[o] & x0) | (ones[o] & x1) | (x0 & x1);
                        ones[o] = ones[o] ^ x0 ^ x1;
                        uint32_t t1 = (ones[o] & x2) | (ones[o] & x3) | (x2 & x3);
                        ones[o] = ones[o] ^ x2 ^ x3;
                        uint32_t f = (twos[o] & t0) | (twos[o] & t1) | (t0 & t1);
                        twos[o] = twos[o] ^ t0 ^ t1;
                        uint32_t pc = (uint32_t)__popc(f);
                        asm("mad.lo.u32 %0, %1, %2, %0;" : "+r"(acc[o]) : "r"(pc), "r"(four));
                    }
                }
            }
        }
    }

    // Epilogue: D = acc + 2*popc(twos) + popc(ones); dot = 4096 - 2D.
    const uint32_t m0 = mtb * 64u + (uint32_t)mrow;
    const uint32_t n0 = ntb * 64u + (uint32_t)ncol;
    #pragma unroll
    for (int mf = 0; mf < 4; mf++) {
        const int o = mf * 4;
        int D0 = (int)acc[o+0] + (__popc(twos[o+0]) << 1) + __popc(ones[o+0]);
        int D1 = (int)acc[o+1] + (__popc(twos[o+1]) << 1) + __popc(ones[o+1]);
        int D2 = (int)acc[o+2] + (__popc(twos[o+2]) << 1) + __popc(ones[o+2]);
        int D3 = (int)acc[o+3] + (__popc(twos[o+3]) << 1) + __popc(ones[o+3]);
        *reinterpret_cast<float4*>(out + (size_t)(m0 + (uint32_t)mf) * NDIM + n0) =
            make_float4((float)(KDIM - 2 * D0), (float)(KDIM - 2 * D1),
                        (float)(KDIM - 2 * D2), (float)(KDIM - 2 * D3));
    }
}

// ---------------------------------------------------------------------------
// Launch
// ---------------------------------------------------------------------------
extern "C" void kernel_launch(void* const* d_in, const int* in_sizes, int n_in,
                              void* d_out, int out_size) {
    const float* x = (const float*)d_in[0];   // [8192, 4096]
    const float* w = (const float*)d_in[1];   // [4096, 4096] (k-major)
    float* out = (float*)d_out;               // [8192, 4096]
    (void)in_sizes; (void)n_in; (void)out_size;

    static constexpr int SMEM = 2 * KW * 64 * 4;   // 65536 B
    cudaFuncSetAttribute(k_bgemm, cudaFuncAttributeMaxDynamicSharedMemorySize, SMEM);

    k_pack<<<3072, 256>>>(x, w);                   // fused x+w pack
    k_bgemm<<<MT * NT, 256, SMEM>>>(out);          // 8192 blocks
}